// round 7
// baseline (speedup 1.0000x reference)
#include <cuda_runtime.h>
#include <cuda_bf16.h>
#include <stdint.h>

#define BB 2
#define SS 2048
#define DD 1024
#define HH 16
#define DH 64

// Pre-split storage: uint2 = { bf16x2(hi0,hi1), bf16x2(lo0,lo1) } per k-pair.
// Stored as uint4 (2 pairs) for 16B cp.async alignment.
__device__ __align__(16) uint4 g_spX[3][BB*SS][DD/4];     // inputs Q,K,V split
__device__ __align__(16) uint4 g_spW[4][DD][DD/4];        // Wq,Wk,Wv,Wo split
__device__ __align__(16) uint4 g_qk[2][BB*HH][SS][DH/4];  // q,k split (q pre-scaled)
__device__ __align__(16) uint4 g_vt[BB*HH][DH][SS/4];     // V^T split
__device__ __align__(16) uint4 g_ctxsp[BB*SS][DD/4];      // context split
__device__ float g_v[BB*HH*SS*DH];                        // fp32 v (prep_vt input)

// ---------------------------------------------------------------------------
// bf16x2 split + 3-term mma (error ~2^-17 per product)
// ---------------------------------------------------------------------------
__device__ __forceinline__ uint32_t pack_bf2(float a, float b) {
    __nv_bfloat162 h;
    h.x = __float2bfloat16_rn(a);
    h.y = __float2bfloat16_rn(b);
    return *reinterpret_cast<uint32_t*>(&h);
}
__device__ __forceinline__ uint2 split2(float x0, float x1) {
    __nv_bfloat16 h0 = __float2bfloat16_rn(x0);
    __nv_bfloat16 h1 = __float2bfloat16_rn(x1);
    uint2 u;
    __nv_bfloat162 hh; hh.x = h0; hh.y = h1;
    u.x = *reinterpret_cast<uint32_t*>(&hh);
    u.y = pack_bf2(x0 - __bfloat162float(h0), x1 - __bfloat162float(h1));
    return u;
}

__device__ __forceinline__ void mma16(float* c,
    uint32_t a0, uint32_t a1, uint32_t a2, uint32_t a3, uint32_t b0, uint32_t b1)
{
    asm volatile(
        "mma.sync.aligned.m16n8k16.row.col.f32.bf16.bf16.f32 "
        "{%0,%1,%2,%3}, {%4,%5,%6,%7}, {%8,%9}, {%0,%1,%2,%3};\n"
        : "+f"(c[0]), "+f"(c[1]), "+f"(c[2]), "+f"(c[3])
        : "r"(a0), "r"(a1), "r"(a2), "r"(a3), "r"(b0), "r"(b1));
}

__device__ __forceinline__ void mma3_bf(float* c, const uint2 qa[4], uint2 qb0, uint2 qb1)
{
    mma16(c, qa[0].x, qa[1].x, qa[2].x, qa[3].x, qb0.x, qb1.x);   // hi*hi
    mma16(c, qa[0].y, qa[1].y, qa[2].y, qa[3].y, qb0.x, qb1.x);   // lo*hi
    mma16(c, qa[0].x, qa[1].x, qa[2].x, qa[3].x, qb0.y, qb1.y);   // hi*lo
}

// ---------------------------------------------------------------------------
// cp.async helpers
// ---------------------------------------------------------------------------
__device__ __forceinline__ void cp16(void* smem_dst, const void* gmem_src) {
    uint32_t s = (uint32_t)__cvta_generic_to_shared(smem_dst);
    asm volatile("cp.async.cg.shared.global [%0], [%1], 16;\n" :: "r"(s), "l"(gmem_src));
}
#define CP_COMMIT() asm volatile("cp.async.commit_group;\n" ::: "memory")
#define CP_WAIT0()  asm volatile("cp.async.wait_group 0;\n" ::: "memory")

// ---------------------------------------------------------------------------
// Pre-split NT GEMM core (projections): C[128,128] += A[128,K]*B[128,K]^T.
// Pad 12 uint2 (24 words): conflict-free LDS.64 fragment loads.
// ---------------------------------------------------------------------------
struct GemmSmem { uint2 As[2][128][12]; uint2 Bs[2][128][12]; };  // 48KB

__device__ __forceinline__ void gemm_sp_core(
    const uint4* __restrict__ A, int lda4,
    const uint4* __restrict__ B, int ldb4,
    int kTiles, GemmSmem& sm, float acc[2][8][4])
{
    const int tid = threadIdx.x;
    const int lane = tid & 31, warp = tid >> 5;
    const int tig = lane & 3, gid = lane >> 2;
    const int wr = (warp & 3) * 32, wc = (warp >> 2) * 64;
    const int fr0 = tid >> 2, fr1 = fr0 + 64, fq = tid & 3;

    auto issue = [&](int s, int kt) {
        const int c = kt * 4 + fq;
        cp16(&sm.As[s][fr0][fq * 2], A + (size_t)fr0 * lda4 + c);
        cp16(&sm.As[s][fr1][fq * 2], A + (size_t)fr1 * lda4 + c);
        cp16(&sm.Bs[s][fr0][fq * 2], B + (size_t)fr0 * ldb4 + c);
        cp16(&sm.Bs[s][fr1][fq * 2], B + (size_t)fr1 * ldb4 + c);
        CP_COMMIT();
    };
    issue(0, 0);
    for (int kt = 0; kt < kTiles; kt++) {
        const int s = kt & 1;
        CP_WAIT0();
        __syncthreads();
        if (kt + 1 < kTiles) issue(s ^ 1, kt + 1);
        uint2 qa[2][4];
        #pragma unroll
        for (int mt = 0; mt < 2; mt++) {
            const int rA = wr + mt * 16 + gid;
            qa[mt][0] = sm.As[s][rA][tig];
            qa[mt][1] = sm.As[s][rA + 8][tig];
            qa[mt][2] = sm.As[s][rA][tig + 4];
            qa[mt][3] = sm.As[s][rA + 8][tig + 4];
        }
        #pragma unroll
        for (int nt = 0; nt < 8; nt++) {
            const int cB = wc + nt * 8 + gid;
            uint2 qb0 = sm.Bs[s][cB][tig];
            uint2 qb1 = sm.Bs[s][cB][tig + 4];
            #pragma unroll
            for (int mt = 0; mt < 2; mt++)
                mma3_bf(acc[mt][nt], qa[mt], qb0, qb1);
        }
    }
}

// ---------------------------------------------------------------------------
// Prep: split inputs X (z=0..2) and weights W (z=3..6).
// ---------------------------------------------------------------------------
__global__ void split_mats_kernel(
    const float* __restrict__ Qin, const float* __restrict__ Kin,
    const float* __restrict__ Vin, const float* __restrict__ Wq,
    const float* __restrict__ Wk, const float* __restrict__ Wv,
    const float* __restrict__ Wo)
{
    const int z = blockIdx.y, row = blockIdx.x;
    if (z >= 3 && row >= DD) return;
    const float* srcs[7] = {Qin, Kin, Vin, Wq, Wk, Wv, Wo};
    float4 v = *(const float4*)(srcs[z] + (size_t)row * DD + threadIdx.x * 4);
    uint2* dst = (z < 3) ? (uint2*)&g_spX[z][row][0] : (uint2*)&g_spW[z - 3][row][0];
    dst[threadIdx.x * 2]     = split2(v.x, v.y);
    dst[threadIdx.x * 2 + 1] = split2(v.z, v.w);
}

// ---------------------------------------------------------------------------
// Prep: transpose+split V -> g_vt [bh][dh][s-pairs]. Runs after qkv.
// ---------------------------------------------------------------------------
__global__ void prep_vt_kernel()
{
    const int bh = blockIdx.y, s0 = blockIdx.x * 8;
    const int dh = threadIdx.x & 63, sp = threadIdx.x >> 6;
    const int s = s0 + 2 * sp;
    const float* vb = g_v + ((size_t)bh * SS + s) * DH + dh;
    uint2* dst = (uint2*)&g_vt[bh][dh][0];
    dst[(s0 >> 1) + sp] = split2(vb[0], vb[DH]);
}

// ---------------------------------------------------------------------------
// QKV projections; writes q,k pre-split (q scaled), v fp32.
// ---------------------------------------------------------------------------
__global__ __launch_bounds__(256, 2) void qkv_proj_kernel(
    const float* __restrict__ bq, const float* __restrict__ bk,
    const float* __restrict__ bv)
{
    extern __shared__ char dynraw[];
    GemmSmem& sm = *reinterpret_cast<GemmSmem*>(dynraw);
    const int z = blockIdx.z;
    const float* bias = (z == 0) ? bq : (z == 1) ? bk : bv;
    const float scale = (z == 0) ? 0.125f : 1.0f;

    const int rowBase = blockIdx.y * 128, colBase = blockIdx.x * 128;
    float acc[2][8][4] = {};
    gemm_sp_core(&g_spX[z][rowBase][0], DD / 4, &g_spW[z][colBase][0], DD / 4,
                 DD / 16, sm, acc);

    const int lane = threadIdx.x & 31, warp = threadIdx.x >> 5;
    const int tig = lane & 3, gid = lane >> 2;
    const int wr = (warp & 3) * 32, wc = (warp >> 2) * 64;
    #pragma unroll
    for (int mt = 0; mt < 2; mt++)
        #pragma unroll
        for (int nt = 0; nt < 8; nt++) {
            int col = colBase + wc + nt * 8 + 2 * tig;
            float2 bb = *(const float2*)&bias[col];
            int h = col >> 6, dh = col & 63;
            #pragma unroll
            for (int half = 0; half < 2; half++) {
                int row = rowBase + wr + mt * 16 + gid + 8 * half;
                int b = row >> 11, s = row & (SS - 1);
                float2 w;
                w.x = (acc[mt][nt][2 * half + 0] + bb.x) * scale;
                w.y = (acc[mt][nt][2 * half + 1] + bb.y) * scale;
                if (z < 2) {
                    uint2* dst = (uint2*)&g_qk[z][b * HH + h][s][0];
                    dst[dh >> 1] = split2(w.x, w.y);
                } else {
                    *(float2*)&g_v[(((size_t)(b * HH + h)) * SS + s) * DH + dh] = w;
                }
            }
        }
}

// ---------------------------------------------------------------------------
// Fused attention strip kernel: one CTA per (bh, 128-row block).
//   Phase S : Q strip resident; stream K tiles; write exp(S) unnorm to attn;
//             accumulate row sums in registers (no psum global).
//   Phase PV: re-read own tiles (L2-hot), normalize, write normalized P,
//             accumulate O = P@V from pre-split V^T. Then zero tail.
// ---------------------------------------------------------------------------
struct FusedSmem {
    union {
        struct { uint2 Qs[128][36]; uint2 Ks[2][128][36]; } sp;   // 110592 B
        struct { uint2 Ps[2][128][12]; uint2 Vs[2][64][12]; } pv; // 36864 B
    } u;
    float rsum[2][128];
    float sinv[128];
};

__global__ __launch_bounds__(256, 2) void attn_fused_kernel(float* __restrict__ scores)
{
    extern __shared__ char dynraw[];
    FusedSmem& sm = *reinterpret_cast<FusedSmem*>(dynraw);

    const int bh = blockIdx.y;
    const int rt = (int)(gridDim.x - 1) - (int)blockIdx.x;   // heavy first
    const int rowBase = rt * 128;
    float* P = scores + (size_t)bh * SS * SS + (size_t)rowBase * SS;
    const uint4* Qg = &g_qk[0][bh][rowBase][0];
    const uint4* Kg = &g_qk[1][bh][0][0];
    const uint4* Vt = &g_vt[bh][0][0];

    const int tid  = threadIdx.x;
    const int lane = tid & 31, warp = tid >> 5;
    const int tig  = lane & 3, gid = lane >> 2;
    const int wr   = (warp & 3) * 32;
    const int grp  = warp >> 2;
    const int wc   = grp * 64;

    // ---- Phase S ----
    #pragma unroll
    for (int i = 0; i < 8; i++) {
        int idx = tid + i * 256;
        int r = idx >> 4, q = idx & 15;
        cp16(&sm.u.sp.Qs[r][q * 2], Qg + (size_t)r * 16 + q);
    }
    CP_COMMIT();
    auto issueK = [&](int s, int ct) {
        #pragma unroll
        for (int i = 0; i < 8; i++) {
            int idx = tid + i * 256;
            int r = idx >> 4, q = idx & 15;
            cp16(&sm.u.sp.Ks[s][r][q * 2], Kg + (size_t)(ct * 128 + r) * 16 + q);
        }
        CP_COMMIT();
    };
    issueK(0, 0);

    float sums[2][2] = {};
    for (int ct = 0; ct <= rt; ct++) {
        const int s = ct & 1;
        CP_WAIT0();
        __syncthreads();
        if (ct < rt) issueK(s ^ 1, ct + 1);

        float acc[2][8][4] = {};
        #pragma unroll
        for (int kk = 0; kk < 4; kk++) {
            const int k0 = kk * 8 + tig;
            uint2 qa[2][4];
            #pragma unroll
            for (int mt = 0; mt < 2; mt++) {
                const int rA = wr + mt * 16 + gid;
                qa[mt][0] = sm.u.sp.Qs[rA][k0];
                qa[mt][1] = sm.u.sp.Qs[rA + 8][k0];
                qa[mt][2] = sm.u.sp.Qs[rA][k0 + 4];
                qa[mt][3] = sm.u.sp.Qs[rA + 8][k0 + 4];
            }
            #pragma unroll
            for (int nt = 0; nt < 8; nt++) {
                const int cB = wc + nt * 8 + gid;
                uint2 qb0 = sm.u.sp.Ks[s][cB][k0];
                uint2 qb1 = sm.u.sp.Ks[s][cB][k0 + 4];
                #pragma unroll
                for (int mt = 0; mt < 2; mt++)
                    mma3_bf(acc[mt][nt], qa[mt], qb0, qb1);
            }
        }
        const bool diag = (ct == rt);
        #pragma unroll
        for (int mt = 0; mt < 2; mt++)
            #pragma unroll
            for (int nt = 0; nt < 8; nt++)
                #pragma unroll
                for (int half = 0; half < 2; half++) {
                    const int rL = wr + mt * 16 + gid + 8 * half;
                    const int cL = wc + nt * 8 + 2 * tig;
                    float p0 = (!diag || cL     <= rL) ? __expf(acc[mt][nt][2*half+0]) : 0.f;
                    float p1 = (!diag || cL + 1 <= rL) ? __expf(acc[mt][nt][2*half+1]) : 0.f;
                    sums[mt][half] += p0 + p1;
                    *(float2*)&P[(size_t)rL * SS + ct * 128 + cL] = make_float2(p0, p1);
                }
    }

    // row-sum reduction (deterministic)
    #pragma unroll
    for (int o = 1; o <= 2; o <<= 1)
        #pragma unroll
        for (int mt = 0; mt < 2; mt++)
            #pragma unroll
            for (int half = 0; half < 2; half++)
                sums[mt][half] += __shfl_xor_sync(0xffffffffu, sums[mt][half], o);
    if (tig == 0)
        #pragma unroll
        for (int mt = 0; mt < 2; mt++)
            #pragma unroll
            for (int half = 0; half < 2; half++)
                sm.rsum[grp][wr + mt * 16 + gid + 8 * half] = sums[mt][half];
    __syncthreads();     // also: all S-phase smem reads done before PV overwrites
    if (tid < 128) sm.sinv[tid] = 1.0f / (sm.rsum[0][tid] + sm.rsum[1][tid]);
    __syncthreads();

    // ---- Phase PV ----
    const int fr0 = tid >> 2, fr1 = fr0 + 64;
    const int fc  = (tid & 3) << 2;
    const int fp  = (tid & 3) << 1;
    const int vr  = tid >> 2, vq = tid & 3;
    const int kTiles = (rt + 1) * 8;
    const float iv0 = sm.sinv[fr0], iv1 = sm.sinv[fr1];

    float4 va0, va1;
    auto prefA = [&](int kt) {
        const float* P2 = P + kt * 16;
        va0 = *(const float4*)(P2 + (size_t)fr0 * SS + fc);
        va1 = *(const float4*)(P2 + (size_t)fr1 * SS + fc);
    };
    auto issueB = [&](int s, int kt) {
        cp16(&sm.u.pv.Vs[s][vr][vq * 2], Vt + (size_t)vr * (SS / 4) + kt * 4 + vq);
        CP_COMMIT();
    };
    auto stashA = [&](int s, int ktI) {
        float4 p0, p1;
        p0.x = va0.x * iv0; p0.y = va0.y * iv0; p0.z = va0.z * iv0; p0.w = va0.w * iv0;
        p1.x = va1.x * iv1; p1.y = va1.y * iv1; p1.z = va1.z * iv1; p1.w = va1.w * iv1;
        *(float4*)(P + (size_t)fr0 * SS + ktI * 16 + fc) = p0;   // normalized attn_prob
        *(float4*)(P + (size_t)fr1 * SS + ktI * 16 + fc) = p1;
        sm.u.pv.Ps[s][fr0][fp]     = split2(p0.x, p0.y);
        sm.u.pv.Ps[s][fr0][fp + 1] = split2(p0.z, p0.w);
        sm.u.pv.Ps[s][fr1][fp]     = split2(p1.x, p1.y);
        sm.u.pv.Ps[s][fr1][fp + 1] = split2(p1.z, p1.w);
    };

    float oacc[8][4] = {};
    prefA(0); issueB(0, 0); stashA(0, 0);
    CP_WAIT0();
    __syncthreads();

    for (int kt = 0; kt < kTiles; kt++) {
        const int s = kt & 1;
        const bool more = (kt + 1 < kTiles);
        if (more) { prefA(kt + 1); issueB(s ^ 1, kt + 1); }
        uint2 qa[4];
        const int rA = warp * 16 + gid;
        qa[0] = sm.u.pv.Ps[s][rA][tig];
        qa[1] = sm.u.pv.Ps[s][rA + 8][tig];
        qa[2] = sm.u.pv.Ps[s][rA][tig + 4];
        qa[3] = sm.u.pv.Ps[s][rA + 8][tig + 4];
        #pragma unroll
        for (int nt = 0; nt < 8; nt++) {
            const int cB = nt * 8 + gid;
            uint2 qb0 = sm.u.pv.Vs[s][cB][tig];
            uint2 qb1 = sm.u.pv.Vs[s][cB][tig + 4];
            mma3_bf(oacc[nt], qa, qb0, qb1);
        }
        if (more) stashA(s ^ 1, kt + 1);
        CP_WAIT0();
        __syncthreads();
    }

    const int b = bh >> 4, h = bh & 15;
    #pragma unroll
    for (int nt = 0; nt < 8; nt++) {
        int col = nt * 8 + 2 * tig;
        #pragma unroll
        for (int half = 0; half < 2; half++) {
            int s = rowBase + warp * 16 + gid + 8 * half;
            float2 w;
            w.x = oacc[nt][2 * half + 0];
            w.y = oacc[nt][2 * half + 1];
            uint2* dst = (uint2*)&g_ctxsp[b * SS + s][0];
            dst[(h * DH + col) >> 1] = split2(w.x, w.y);
        }
    }

    // ---- zero tail (masked cols beyond the diagonal block) ----
    {
        const int tailBase = (rt + 1) * 128;
        const int tailCols = SS - tailBase;
        if (tailCols > 0) {
            const float4 z = make_float4(0.f, 0.f, 0.f, 0.f);
            for (int r = warp; r < 128; r += 8) {
                float* rp = P + (size_t)r * SS + tailBase;
                for (int c = lane * 4; c < tailCols; c += 128)
                    *(float4*)(rp + c) = z;
            }
        }
    }
}

// ---------------------------------------------------------------------------
// Output projection from pre-split ctx and Wo.
// ---------------------------------------------------------------------------
__global__ __launch_bounds__(256, 2) void outproj_kernel(
    const float* __restrict__ bo, float* __restrict__ out)
{
    extern __shared__ char dynraw[];
    GemmSmem& sm = *reinterpret_cast<GemmSmem*>(dynraw);
    const int rowBase = blockIdx.y * 128, colBase = blockIdx.x * 128;
    float acc[2][8][4] = {};
    gemm_sp_core(&g_ctxsp[rowBase][0], DD / 4, &g_spW[3][colBase][0], DD / 4,
                 DD / 16, sm, acc);

    const int lane = threadIdx.x & 31, warp = threadIdx.x >> 5;
    const int tig = lane & 3, gid = lane >> 2;
    const int wr = (warp & 3) * 32, wc = (warp >> 2) * 64;
    #pragma unroll
    for (int mt = 0; mt < 2; mt++)
        #pragma unroll
        for (int nt = 0; nt < 8; nt++) {
            int col = colBase + wc + nt * 8 + 2 * tig;
            float2 bb = *(const float2*)&bo[col];
            #pragma unroll
            for (int half = 0; half < 2; half++) {
                int row = rowBase + wr + mt * 16 + gid + 8 * half;
                float2 w;
                w.x = acc[mt][nt][2 * half + 0] + bb.x;
                w.y = acc[mt][nt][2 * half + 1] + bb.y;
                *(float2*)&out[(size_t)row * DD + col] = w;
            }
        }
}

// ---------------------------------------------------------------------------
extern "C" void kernel_launch(void* const* d_in, const int* in_sizes, int n_in,
                              void* d_out, int out_size)
{
    const float* Q  = (const float*)d_in[0];
    const float* K  = (const float*)d_in[1];
    const float* V  = (const float*)d_in[2];
    // d_in[3] = attn_mask: causal triu(k=1); applied analytically, not read.
    const float* Wq = (const float*)d_in[4];
    const float* bq = (const float*)d_in[5];
    const float* Wk = (const float*)d_in[6];
    const float* bk = (const float*)d_in[7];
    const float* Wv = (const float*)d_in[8];
    const float* bv = (const float*)d_in[9];
    const float* Wo = (const float*)d_in[10];
    const float* bo = (const float*)d_in[11];

    float* out  = (float*)d_out;                       // [B,S,D]
    float* attn = out + (size_t)BB * SS * DD;          // [B,H,S,S]

    const int GSM = (int)sizeof(GemmSmem);             // 48KB
    const int FSM = (int)sizeof(FusedSmem);            // ~110KB
    cudaFuncSetAttribute(qkv_proj_kernel,   cudaFuncAttributeMaxDynamicSharedMemorySize, GSM);
    cudaFuncSetAttribute(attn_fused_kernel, cudaFuncAttributeMaxDynamicSharedMemorySize, FSM);
    cudaFuncSetAttribute(outproj_kernel,    cudaFuncAttributeMaxDynamicSharedMemorySize, GSM);

    split_mats_kernel<<<dim3(BB*SS, 7), 256>>>(Q, K, V, Wq, Wk, Wv, Wo);
    qkv_proj_kernel  <<<dim3(DD/128, (BB*SS)/128, 3), 256, GSM>>>(bq, bk, bv);
    prep_vt_kernel   <<<dim3(SS/8, BB*HH), 256>>>();
    attn_fused_kernel<<<dim3(SS/128, BB*HH), 256, FSM>>>(attn);
    outproj_kernel   <<<dim3(DD/128, (BB*SS)/128), 256, GSM>>>(bo, out);
}

// round 10
// speedup vs baseline: 1.0066x; 1.0066x over previous
#include <cuda_runtime.h>
#include <cuda_bf16.h>
#include <stdint.h>

#define BB 2
#define SS 2048
#define DD 1024
#define HH 16
#define DH 64

// Pre-split storage: uint2 = { bf16x2(hi0,hi1), bf16x2(lo0,lo1) } per k-pair.
__device__ __align__(16) uint4 g_spX[3][BB*SS][DD/4];     // inputs Q,K,V split
__device__ __align__(16) uint4 g_spW[4][DD][DD/4];        // Wq,Wk,Wv,Wo split
__device__ __align__(16) uint4 g_qk[2][BB*HH][SS][DH/4];  // q,k split (q pre-scaled)
__device__ __align__(16) uint4 g_vt[BB*HH][DH][SS/4];     // V^T split
__device__ __align__(16) uint4 g_ctxsp[BB*SS][DD/4];      // context split
__device__ float g_v[BB*HH*SS*DH];                        // fp32 v (prep_vt input)
__device__ float g_psum[(size_t)BB*HH*16*128*16];         // partial row sums

// ---------------------------------------------------------------------------
// bf16x2 split + 3-term mma (error ~2^-17 per product)
// ---------------------------------------------------------------------------
__device__ __forceinline__ uint32_t pack_bf2(float a, float b) {
    __nv_bfloat162 h;
    h.x = __float2bfloat16_rn(a);
    h.y = __float2bfloat16_rn(b);
    return *reinterpret_cast<uint32_t*>(&h);
}
__device__ __forceinline__ uint2 split2(float x0, float x1) {
    __nv_bfloat16 h0 = __float2bfloat16_rn(x0);
    __nv_bfloat16 h1 = __float2bfloat16_rn(x1);
    uint2 u;
    __nv_bfloat162 hh; hh.x = h0; hh.y = h1;
    u.x = *reinterpret_cast<uint32_t*>(&hh);
    u.y = pack_bf2(x0 - __bfloat162float(h0), x1 - __bfloat162float(h1));
    return u;
}

__device__ __forceinline__ void mma16(float* c,
    uint32_t a0, uint32_t a1, uint32_t a2, uint32_t a3, uint32_t b0, uint32_t b1)
{
    asm volatile(
        "mma.sync.aligned.m16n8k16.row.col.f32.bf16.bf16.f32 "
        "{%0,%1,%2,%3}, {%4,%5,%6,%7}, {%8,%9}, {%0,%1,%2,%3};\n"
        : "+f"(c[0]), "+f"(c[1]), "+f"(c[2]), "+f"(c[3])
        : "r"(a0), "r"(a1), "r"(a2), "r"(a3), "r"(b0), "r"(b1));
}

__device__ __forceinline__ void mma3_bf(float* c, const uint2 qa[4], uint2 qb0, uint2 qb1)
{
    mma16(c, qa[0].x, qa[1].x, qa[2].x, qa[3].x, qb0.x, qb1.x);   // hi*hi
    mma16(c, qa[0].y, qa[1].y, qa[2].y, qa[3].y, qb0.x, qb1.x);   // lo*hi
    mma16(c, qa[0].x, qa[1].x, qa[2].x, qa[3].x, qb0.y, qb1.y);   // hi*lo
}

// cp.async helpers
__device__ __forceinline__ void cp16(void* smem_dst, const void* gmem_src) {
    uint32_t s = (uint32_t)__cvta_generic_to_shared(smem_dst);
    asm volatile("cp.async.cg.shared.global [%0], [%1], 16;\n" :: "r"(s), "l"(gmem_src));
}
#define CP_COMMIT() asm volatile("cp.async.commit_group;\n" ::: "memory")
#define CP_WAIT(n)  asm volatile("cp.async.wait_group %0;\n" :: "n"(n) : "memory")

// ---------------------------------------------------------------------------
// 3-stage pre-split NT GEMM core (projections): C[128,128] += A*B^T.
// Row stride 12 uint2 = 96B -> every cp.async dst 16B-aligned.
// Issue 2 chunks ahead; wait_group 1 -> ~2 chunk-times of latency cover.
// ---------------------------------------------------------------------------
struct GemmSmem3 { uint2 As[3][128][12]; uint2 Bs[3][128][12]; };   // 73728 B

__device__ __forceinline__ void gemm_sp_core3(
    const uint4* __restrict__ A, int lda4,
    const uint4* __restrict__ B, int ldb4,
    int kTiles, GemmSmem3& sm, float acc[2][8][4])
{
    const int tid = threadIdx.x;
    const int lane = tid & 31, warp = tid >> 5;
    const int tig = lane & 3, gid = lane >> 2;
    const int wr = (warp & 3) * 32, wc = (warp >> 2) * 64;
    const int fr0 = tid >> 2, fr1 = fr0 + 64, fq = tid & 3;

    auto issue = [&](int st, int kt) {
        const int c = kt * 4 + fq;
        cp16(&sm.As[st][fr0][fq * 2], A + (size_t)fr0 * lda4 + c);
        cp16(&sm.As[st][fr1][fq * 2], A + (size_t)fr1 * lda4 + c);
        cp16(&sm.Bs[st][fr0][fq * 2], B + (size_t)fr0 * ldb4 + c);
        cp16(&sm.Bs[st][fr1][fq * 2], B + (size_t)fr1 * ldb4 + c);
        CP_COMMIT();
    };
    issue(0, 0);
    if (kTiles > 1) issue(1, 1);

    for (int kt = 0; kt < kTiles; kt++) {
        const int s = kt % 3;
        if (kt < kTiles - 1) CP_WAIT(1); else CP_WAIT(0);
        __syncthreads();
        if (kt + 2 < kTiles) issue((kt + 2) % 3, kt + 2);
        uint2 qa[2][4];
        #pragma unroll
        for (int mt = 0; mt < 2; mt++) {
            const int rA = wr + mt * 16 + gid;
            qa[mt][0] = sm.As[s][rA][tig];
            qa[mt][1] = sm.As[s][rA + 8][tig];
            qa[mt][2] = sm.As[s][rA][tig + 4];
            qa[mt][3] = sm.As[s][rA + 8][tig + 4];
        }
        #pragma unroll
        for (int nt = 0; nt < 8; nt++) {
            const int cB = wc + nt * 8 + gid;
            uint2 qb0 = sm.Bs[s][cB][tig];
            uint2 qb1 = sm.Bs[s][cB][tig + 4];
            #pragma unroll
            for (int mt = 0; mt < 2; mt++)
                mma3_bf(acc[mt][nt], qa[mt], qb0, qb1);
        }
    }
}

// ---------------------------------------------------------------------------
// Prep: split inputs X (z=0..2) and weights W (z=3..6).
// ---------------------------------------------------------------------------
__global__ void split_mats_kernel(
    const float* __restrict__ Qin, const float* __restrict__ Kin,
    const float* __restrict__ Vin, const float* __restrict__ Wq,
    const float* __restrict__ Wk, const float* __restrict__ Wv,
    const float* __restrict__ Wo)
{
    const int z = blockIdx.y, row = blockIdx.x;
    if (z >= 3 && row >= DD) return;
    const float* srcs[7] = {Qin, Kin, Vin, Wq, Wk, Wv, Wo};
    float4 v = *(const float4*)(srcs[z] + (size_t)row * DD + threadIdx.x * 4);
    uint2* dst = (z < 3) ? (uint2*)&g_spX[z][row][0] : (uint2*)&g_spW[z - 3][row][0];
    dst[threadIdx.x * 2]     = split2(v.x, v.y);
    dst[threadIdx.x * 2 + 1] = split2(v.z, v.w);
}

// ---------------------------------------------------------------------------
// Prep: transpose+split V -> g_vt [bh][dh][s-pairs]. Runs after qkv.
// ---------------------------------------------------------------------------
__global__ void prep_vt_kernel()
{
    const int bh = blockIdx.y, s0 = blockIdx.x * 8;
    const int dh = threadIdx.x & 63, sp = threadIdx.x >> 6;
    const int s = s0 + 2 * sp;
    const float* vb = g_v + ((size_t)bh * SS + s) * DH + dh;
    uint2* dst = (uint2*)&g_vt[bh][dh][0];
    dst[(s0 >> 1) + sp] = split2(vb[0], vb[DH]);
}

// ---------------------------------------------------------------------------
// QKV projections; writes q,k pre-split (q scaled), v fp32.
// ---------------------------------------------------------------------------
__global__ __launch_bounds__(256, 2) void qkv_proj_kernel(
    const float* __restrict__ bq, const float* __restrict__ bk,
    const float* __restrict__ bv)
{
    extern __shared__ char dynraw[];
    GemmSmem3& sm = *reinterpret_cast<GemmSmem3*>(dynraw);
    const int z = blockIdx.z;
    const float* bias = (z == 0) ? bq : (z == 1) ? bk : bv;
    const float scale = (z == 0) ? 0.125f : 1.0f;

    const int rowBase = blockIdx.y * 128, colBase = blockIdx.x * 128;
    float acc[2][8][4] = {};
    gemm_sp_core3(&g_spX[z][rowBase][0], DD / 4, &g_spW[z][colBase][0], DD / 4,
                  DD / 16, sm, acc);

    const int lane = threadIdx.x & 31, warp = threadIdx.x >> 5;
    const int tig = lane & 3, gid = lane >> 2;
    const int wr = (warp & 3) * 32, wc = (warp >> 2) * 64;
    #pragma unroll
    for (int mt = 0; mt < 2; mt++)
        #pragma unroll
        for (int nt = 0; nt < 8; nt++) {
            int col = colBase + wc + nt * 8 + 2 * tig;
            float2 bb = *(const float2*)&bias[col];
            int h = col >> 6, dh = col & 63;
            #pragma unroll
            for (int half = 0; half < 2; half++) {
                int row = rowBase + wr + mt * 16 + gid + 8 * half;
                int b = row >> 11, s = row & (SS - 1);
                float2 w;
                w.x = (acc[mt][nt][2 * half + 0] + bb.x) * scale;
                w.y = (acc[mt][nt][2 * half + 1] + bb.y) * scale;
                if (z < 2) {
                    uint2* dst = (uint2*)&g_qk[z][b * HH + h][s][0];
                    dst[dh >> 1] = split2(w.x, w.y);
                } else {
                    *(float2*)&g_v[(((size_t)(b * HH + h)) * SS + s) * DH + dh] = w;
                }
            }
        }
}

// ---------------------------------------------------------------------------
// Scores: one-shot smem load (K=64 fits entirely), then 4 straight MMA chunks.
// Writes P_unnorm = exp(q@k^T) + partial row sums. Upper tiles write zeros.
// ---------------------------------------------------------------------------
struct ScoreSmem { uint2 As[4][128][12]; uint2 Bs[4][128][12]; };   // 98304 B

__global__ __launch_bounds__(256, 2) void score_kernel(float* __restrict__ scores)
{
    const int bh = blockIdx.z, rt = blockIdx.y, ct = blockIdx.x;
    float* outp = scores + (size_t)bh * SS * SS;

    if (ct > rt) {      // masked block: write exact zeros
        const int rowBase = rt * 128, colBase = ct * 128;
        const float4 z = make_float4(0.f, 0.f, 0.f, 0.f);
        #pragma unroll
        for (int i = 0; i < 8; i++) {
            int idx = threadIdx.x + i * 256;
            int r = idx >> 4, c4 = idx & 15;
            *(float4*)&outp[(size_t)(rowBase + r) * SS + colBase + c4 * 4] = z;
        }
        return;
    }

    extern __shared__ char dynraw[];
    ScoreSmem& sm = *reinterpret_cast<ScoreSmem*>(dynraw);
    __shared__ float rsum[2][128];

    const int rowBase = rt * 128, colBase = ct * 128;
    const uint4* A = &g_qk[0][bh][rowBase][0];
    const uint4* B = &g_qk[1][bh][colBase][0];

    const int tid = threadIdx.x;
    const int lane = tid & 31, warp = tid >> 5;
    const int tig = lane & 3, gid = lane >> 2;
    const int wr = (warp & 3) * 32, grp = warp >> 2, wc = grp * 64;
    const int fr0 = tid >> 2, fr1 = fr0 + 64, fq = tid & 3;

    // one-shot load of the full q and k tiles (4 chunks each)
    #pragma unroll
    for (int c = 0; c < 4; c++) {
        const int col = c * 4 + fq;
        cp16(&sm.As[c][fr0][fq * 2], A + (size_t)fr0 * 16 + col);
        cp16(&sm.As[c][fr1][fq * 2], A + (size_t)fr1 * 16 + col);
        cp16(&sm.Bs[c][fr0][fq * 2], B + (size_t)fr0 * 16 + col);
        cp16(&sm.Bs[c][fr1][fq * 2], B + (size_t)fr1 * 16 + col);
    }
    CP_COMMIT();
    CP_WAIT(0);
    __syncthreads();

    float acc[2][8][4] = {};
    #pragma unroll
    for (int c = 0; c < 4; c++) {
        uint2 qa[2][4];
        #pragma unroll
        for (int mt = 0; mt < 2; mt++) {
            const int rA = wr + mt * 16 + gid;
            qa[mt][0] = sm.As[c][rA][tig];
            qa[mt][1] = sm.As[c][rA + 8][tig];
            qa[mt][2] = sm.As[c][rA][tig + 4];
            qa[mt][3] = sm.As[c][rA + 8][tig + 4];
        }
        #pragma unroll
        for (int nt = 0; nt < 8; nt++) {
            const int cB = wc + nt * 8 + gid;
            uint2 qb0 = sm.Bs[c][cB][tig];
            uint2 qb1 = sm.Bs[c][cB][tig + 4];
            #pragma unroll
            for (int mt = 0; mt < 2; mt++)
                mma3_bf(acc[mt][nt], qa[mt], qb0, qb1);
        }
    }

    const bool diag = (rt == ct);
    float sums[2][2] = {};
    #pragma unroll
    for (int mt = 0; mt < 2; mt++)
        #pragma unroll
        for (int nt = 0; nt < 8; nt++)
            #pragma unroll
            for (int half = 0; half < 2; half++) {
                const int rL = wr + mt * 16 + gid + 8 * half;
                const int cL = wc + nt * 8 + 2 * tig;
                float p0 = (!diag || cL     <= rL) ? __expf(acc[mt][nt][2*half+0]) : 0.f;
                float p1 = (!diag || cL + 1 <= rL) ? __expf(acc[mt][nt][2*half+1]) : 0.f;
                sums[mt][half] += p0 + p1;
                *(float2*)&outp[(size_t)(rowBase + rL) * SS + colBase + cL] =
                    make_float2(p0, p1);
            }
    #pragma unroll
    for (int o = 1; o <= 2; o <<= 1)
        #pragma unroll
        for (int mt = 0; mt < 2; mt++)
            #pragma unroll
            for (int half = 0; half < 2; half++)
                sums[mt][half] += __shfl_xor_sync(0xffffffffu, sums[mt][half], o);
    if (tig == 0)
        #pragma unroll
        for (int mt = 0; mt < 2; mt++)
            #pragma unroll
            for (int half = 0; half < 2; half++)
                rsum[grp][wr + mt * 16 + gid + 8 * half] = sums[mt][half];
    __syncthreads();
    if (tid < 128)
        g_psum[(((size_t)(bh * 16 + rt) * 128) + tid) * 16 + ct] =
            rsum[0][tid] + rsum[1][tid];
}

// ---------------------------------------------------------------------------
// Context: normalize P on the fly (writes normalized attn_prob back),
// O = P@V. P prefetched 2 chunks ahead in regs; V 4-stage cp.async (3 ahead).
// ---------------------------------------------------------------------------
struct CtxSmem { uint2 Ps[2][128][12]; uint2 Vs[4][64][12]; float sinv[128]; };

__global__ __launch_bounds__(256, 2) void context_kernel(float* __restrict__ scores)
{
    __shared__ CtxSmem sm;

    const int bh = blockIdx.z;
    const int rb = (int)(gridDim.x - 1) - (int)blockIdx.x;   // heavy first
    const int rowBase = rb * 128;
    float* P = scores + (size_t)bh * SS * SS + (size_t)rowBase * SS;
    const uint4* Vt = &g_vt[bh][0][0];
    const int kT = (rb + 1) * 8;     // >= 8 always

    const int tid  = threadIdx.x;
    const int lane = tid & 31, warp = tid >> 5;
    const int tig  = lane & 3, gid = lane >> 2;
    const int fr0  = tid >> 2, fr1 = fr0 + 64;
    const int fc   = (tid & 3) << 2;
    const int fp   = (tid & 3) << 1;
    const int vr   = tid >> 2, vq = tid & 3;

    if (tid < 128) {
        const float* pp = &g_psum[(((size_t)(bh * 16 + rb) * 128) + tid) * 16];
        float l = 0.f;
        for (int c = 0; c <= rb; c++) l += pp[c];
        sm.sinv[tid] = 1.0f / l;
    }
    __syncthreads();
    const float iv0 = sm.sinv[fr0], iv1 = sm.sinv[fr1];

    float4 vaA[2], vaB[2];      // two in-flight P chunks (register prefetch)
    auto prefA = [&](float4* va, int kt) {
        const float* P2 = P + kt * 16;
        va[0] = *(const float4*)(P2 + (size_t)fr0 * SS + fc);
        va[1] = *(const float4*)(P2 + (size_t)fr1 * SS + fc);
    };
    auto issueV = [&](int st, int kt) {
        cp16(&sm.Vs[st][vr][vq * 2], Vt + (size_t)vr * (SS / 4) + kt * 4 + vq);
        CP_COMMIT();
    };
    auto stashA = [&](const float4* va, int ktI) {
        float4 p0, p1;
        p0.x = va[0].x * iv0; p0.y = va[0].y * iv0; p0.z = va[0].z * iv0; p0.w = va[0].w * iv0;
        p1.x = va[1].x * iv1; p1.y = va[1].y * iv1; p1.z = va[1].z * iv1; p1.w = va[1].w * iv1;
        *(float4*)(P + (size_t)fr0 * SS + ktI * 16 + fc) = p0;   // normalized attn_prob
        *(float4*)(P + (size_t)fr1 * SS + ktI * 16 + fc) = p1;
        const int s = ktI & 1;
        sm.Ps[s][fr0][fp]     = split2(p0.x, p0.y);
        sm.Ps[s][fr0][fp + 1] = split2(p0.z, p0.w);
        sm.Ps[s][fr1][fp]     = split2(p1.x, p1.y);
        sm.Ps[s][fr1][fp + 1] = split2(p1.z, p1.w);
    };

    // prologue (kT >= 8 so no guards needed)
    prefA(vaA, 0);               // chunk 0 -> slot A (0&1==0)
    stashA(vaA, 0);
    prefA(vaB, 1);               // chunk 1 -> slot B
    prefA(vaA, 2);               // chunk 2 -> slot A
    issueV(0, 0); issueV(1, 1); issueV(2, 2);
    CP_WAIT(2);                  // V chunk 0 ready
    __syncthreads();

    float oacc[8][4] = {};
    for (int kt = 0; kt < kT; kt++) {
        const int sp = kt & 1, sv = kt & 3;
        // MMA on chunk kt
        uint2 qa[4];
        const int rA = warp * 16 + gid;
        qa[0] = sm.Ps[sp][rA][tig];
        qa[1] = sm.Ps[sp][rA + 8][tig];
        qa[2] = sm.Ps[sp][rA][tig + 4];
        qa[3] = sm.Ps[sp][rA + 8][tig + 4];
        #pragma unroll
        for (int nt = 0; nt < 8; nt++) {
            const int cB = nt * 8 + gid;
            uint2 qb0 = sm.Vs[sv][cB][tig];
            uint2 qb1 = sm.Vs[sv][cB][tig + 4];
            mma3_bf(oacc[nt], qa, qb0, qb1);
        }
        // pipeline maintenance
        float4* vaN = ((kt + 1) & 1) ? vaB : vaA;
        if (kt + 1 < kT) stashA(vaN, kt + 1);
        if (kt + 3 < kT) { prefA(vaN, kt + 3); issueV((kt + 3) & 3, kt + 3); }
        if (kt + 3 < kT)      CP_WAIT(2);
        else if (kt + 2 < kT) CP_WAIT(1);
        else                  CP_WAIT(0);
        __syncthreads();
    }

    const int b = bh >> 4, h = bh & 15;
    #pragma unroll
    for (int nt = 0; nt < 8; nt++) {
        int col = nt * 8 + 2 * tig;
        #pragma unroll
        for (int half = 0; half < 2; half++) {
            int s = rowBase + warp * 16 + gid + 8 * half;
            uint2* dst = (uint2*)&g_ctxsp[b * SS + s][0];
            dst[(h * DH + col) >> 1] = split2(oacc[nt][2 * half + 0],
                                              oacc[nt][2 * half + 1]);
        }
    }
}

// ---------------------------------------------------------------------------
// Output projection from pre-split ctx and Wo.
// ---------------------------------------------------------------------------
__global__ __launch_bounds__(256, 2) void outproj_kernel(
    const float* __restrict__ bo, float* __restrict__ out)
{
    extern __shared__ char dynraw[];
    GemmSmem3& sm = *reinterpret_cast<GemmSmem3*>(dynraw);
    const int rowBase = blockIdx.y * 128, colBase = blockIdx.x * 128;
    float acc[2][8][4] = {};
    gemm_sp_core3(&g_ctxsp[rowBase][0], DD / 4, &g_spW[3][colBase][0], DD / 4,
                  DD / 16, sm, acc);

    const int lane = threadIdx.x & 31, warp = threadIdx.x >> 5;
    const int tig = lane & 3, gid = lane >> 2;
    const int wr = (warp & 3) * 32, wc = (warp >> 2) * 64;
    #pragma unroll
    for (int mt = 0; mt < 2; mt++)
        #pragma unroll
        for (int nt = 0; nt < 8; nt++) {
            int col = colBase + wc + nt * 8 + 2 * tig;
            float2 bb = *(const float2*)&bo[col];
            #pragma unroll
            for (int half = 0; half < 2; half++) {
                int row = rowBase + wr + mt * 16 + gid + 8 * half;
                float2 w;
                w.x = acc[mt][nt][2 * half + 0] + bb.x;
                w.y = acc[mt][nt][2 * half + 1] + bb.y;
                *(float2*)&out[(size_t)row * DD + col] = w;
            }
        }
}

// ---------------------------------------------------------------------------
extern "C" void kernel_launch(void* const* d_in, const int* in_sizes, int n_in,
                              void* d_out, int out_size)
{
    const float* Q  = (const float*)d_in[0];
    const float* K  = (const float*)d_in[1];
    const float* V  = (const float*)d_in[2];
    // d_in[3] = attn_mask: causal triu(k=1); applied analytically, not read.
    const float* Wq = (const float*)d_in[4];
    const float* bq = (const float*)d_in[5];
    const float* Wk = (const float*)d_in[6];
    const float* bk = (const float*)d_in[7];
    const float* Wv = (const float*)d_in[8];
    const float* bv = (const float*)d_in[9];
    const float* Wo = (const float*)d_in[10];
    const float* bo = (const float*)d_in[11];

    float* out  = (float*)d_out;                       // [B,S,D]
    float* attn = out + (size_t)BB * SS * DD;          // [B,H,S,S]

    const int GSM = (int)sizeof(GemmSmem3);            // 72KB
    const int SSM = (int)sizeof(ScoreSmem);            // 96KB
    cudaFuncSetAttribute(qkv_proj_kernel, cudaFuncAttributeMaxDynamicSharedMemorySize, GSM);
    cudaFuncSetAttribute(score_kernel,    cudaFuncAttributeMaxDynamicSharedMemorySize, SSM);
    cudaFuncSetAttribute(outproj_kernel,  cudaFuncAttributeMaxDynamicSharedMemorySize, GSM);

    split_mats_kernel<<<dim3(BB*SS, 7), 256>>>(Q, K, V, Wq, Wk, Wv, Wo);
    qkv_proj_kernel <<<dim3(DD/128, (BB*SS)/128, 3), 256, GSM>>>(bq, bk, bv);
    prep_vt_kernel  <<<dim3(SS/8, BB*HH), 256>>>();
    score_kernel    <<<dim3(SS/128, SS/128, BB*HH), 256, SSM>>>(attn);
    context_kernel  <<<dim3(SS/128, 1, BB*HH), 256>>>(attn);
    outproj_kernel  <<<dim3(DD/128, (BB*SS)/128), 256, GSM>>>(bo, out);
}

// round 11
// speedup vs baseline: 1.0717x; 1.0647x over previous
#include <cuda_runtime.h>
#include <cuda_bf16.h>
#include <stdint.h>

#define BB 2
#define SS 2048
#define DD 1024
#define HH 16
#define DH 64

// Pre-split storage: uint2 = { bf16x2(hi0,hi1), bf16x2(lo0,lo1) } per k-pair.
// Stored as uint4 (2 pairs) for 16B cp.async alignment.
__device__ __align__(16) uint4 g_spX[3][BB*SS][DD/4];     // inputs Q,K,V split
__device__ __align__(16) uint4 g_spW[4][DD][DD/4];        // Wq,Wk,Wv,Wo split
__device__ __align__(16) uint4 g_qk[2][BB*HH][SS][DH/4];  // q,k split (q pre-scaled)
__device__ __align__(16) uint4 g_vt[BB*HH][DH][SS/4];     // V^T split
__device__ __align__(16) uint4 g_ctxsp[BB*SS][DD/4];      // context split
__device__ float g_v[BB*HH*SS*DH];                        // fp32 v (prep_vt input)
__device__ float g_psum[(size_t)BB*HH*16*128*16];         // partial row sums

// ---------------------------------------------------------------------------
// bf16x2 split + 3-term mma (error ~2^-17 per product)
// ---------------------------------------------------------------------------
__device__ __forceinline__ uint32_t pack_bf2(float a, float b) {
    __nv_bfloat162 h;
    h.x = __float2bfloat16_rn(a);
    h.y = __float2bfloat16_rn(b);
    return *reinterpret_cast<uint32_t*>(&h);
}
__device__ __forceinline__ uint2 split2(float x0, float x1) {
    __nv_bfloat16 h0 = __float2bfloat16_rn(x0);
    __nv_bfloat16 h1 = __float2bfloat16_rn(x1);
    uint2 u;
    __nv_bfloat162 hh; hh.x = h0; hh.y = h1;
    u.x = *reinterpret_cast<uint32_t*>(&hh);
    u.y = pack_bf2(x0 - __bfloat162float(h0), x1 - __bfloat162float(h1));
    return u;
}

__device__ __forceinline__ float ex2f(float x) {
    float y;
    asm("ex2.approx.f32 %0, %1;" : "=f"(y) : "f"(x));
    return y;
}

__device__ __forceinline__ void mma16(float* c,
    uint32_t a0, uint32_t a1, uint32_t a2, uint32_t a3, uint32_t b0, uint32_t b1)
{
    asm volatile(
        "mma.sync.aligned.m16n8k16.row.col.f32.bf16.bf16.f32 "
        "{%0,%1,%2,%3}, {%4,%5,%6,%7}, {%8,%9}, {%0,%1,%2,%3};\n"
        : "+f"(c[0]), "+f"(c[1]), "+f"(c[2]), "+f"(c[3])
        : "r"(a0), "r"(a1), "r"(a2), "r"(a3), "r"(b0), "r"(b1));
}

__device__ __forceinline__ void mma3_bf(float* c, const uint2 qa[4], uint2 qb0, uint2 qb1)
{
    mma16(c, qa[0].x, qa[1].x, qa[2].x, qa[3].x, qb0.x, qb1.x);   // hi*hi
    mma16(c, qa[0].y, qa[1].y, qa[2].y, qa[3].y, qb0.x, qb1.x);   // lo*hi
    mma16(c, qa[0].x, qa[1].x, qa[2].x, qa[3].x, qb0.y, qb1.y);   // hi*lo
}

// cp.async helpers
__device__ __forceinline__ void cp16(void* smem_dst, const void* gmem_src) {
    uint32_t s = (uint32_t)__cvta_generic_to_shared(smem_dst);
    asm volatile("cp.async.cg.shared.global [%0], [%1], 16;\n" :: "r"(s), "l"(gmem_src));
}
#define CP_COMMIT() asm volatile("cp.async.commit_group;\n" ::: "memory")
#define CP_WAIT0()  asm volatile("cp.async.wait_group 0;\n" ::: "memory")

// ---------------------------------------------------------------------------
// Pre-split NT GEMM core: C[128,128] += A[128,K] * B[128,K]^T from split bufs.
// Pad 12 uint2 (96B rows, 16B-aligned cp.async dsts). Double-buffered.
// ---------------------------------------------------------------------------
struct GemmSmem { uint2 As[2][128][12]; uint2 Bs[2][128][12]; };  // 48KB

__device__ __forceinline__ void gemm_sp_core(
    const uint4* __restrict__ A, int lda4,
    const uint4* __restrict__ B, int ldb4,
    int kTiles, GemmSmem& sm, float acc[2][8][4])
{
    const int tid = threadIdx.x;
    const int lane = tid & 31, warp = tid >> 5;
    const int tig = lane & 3, gid = lane >> 2;
    const int wr = (warp & 3) * 32, wc = (warp >> 2) * 64;
    const int fr0 = tid >> 2, fr1 = fr0 + 64, fq = tid & 3;

    auto issue = [&](int s, int kt) {
        const int c = kt * 4 + fq;
        cp16(&sm.As[s][fr0][fq * 2], A + (size_t)fr0 * lda4 + c);
        cp16(&sm.As[s][fr1][fq * 2], A + (size_t)fr1 * lda4 + c);
        cp16(&sm.Bs[s][fr0][fq * 2], B + (size_t)fr0 * ldb4 + c);
        cp16(&sm.Bs[s][fr1][fq * 2], B + (size_t)fr1 * ldb4 + c);
        CP_COMMIT();
    };
    issue(0, 0);
    for (int kt = 0; kt < kTiles; kt++) {
        const int s = kt & 1;
        CP_WAIT0();
        __syncthreads();
        if (kt + 1 < kTiles) issue(s ^ 1, kt + 1);
        uint2 qa[2][4];
        #pragma unroll
        for (int mt = 0; mt < 2; mt++) {
            const int rA = wr + mt * 16 + gid;
            qa[mt][0] = sm.As[s][rA][tig];
            qa[mt][1] = sm.As[s][rA + 8][tig];
            qa[mt][2] = sm.As[s][rA][tig + 4];
            qa[mt][3] = sm.As[s][rA + 8][tig + 4];
        }
        #pragma unroll
        for (int nt = 0; nt < 8; nt++) {
            const int cB = wc + nt * 8 + gid;
            uint2 qb0 = sm.Bs[s][cB][tig];
            uint2 qb1 = sm.Bs[s][cB][tig + 4];
            #pragma unroll
            for (int mt = 0; mt < 2; mt++)
                mma3_bf(acc[mt][nt], qa[mt], qb0, qb1);
        }
    }
}

// ---------------------------------------------------------------------------
// Prep: split inputs X (z=0..2) and weights W (z=3..6) into global split bufs.
// ---------------------------------------------------------------------------
__global__ void split_mats_kernel(
    const float* __restrict__ Qin, const float* __restrict__ Kin,
    const float* __restrict__ Vin, const float* __restrict__ Wq,
    const float* __restrict__ Wk, const float* __restrict__ Wv,
    const float* __restrict__ Wo)
{
    const int z = blockIdx.y, row = blockIdx.x;
    if (z >= 3 && row >= DD) return;
    const float* srcs[7] = {Qin, Kin, Vin, Wq, Wk, Wv, Wo};
    float4 v = *(const float4*)(srcs[z] + (size_t)row * DD + threadIdx.x * 4);
    uint2* dst = (z < 3) ? (uint2*)&g_spX[z][row][0] : (uint2*)&g_spW[z - 3][row][0];
    dst[threadIdx.x * 2]     = split2(v.x, v.y);
    dst[threadIdx.x * 2 + 1] = split2(v.z, v.w);
}

// ---------------------------------------------------------------------------
// Prep: transpose+split V -> g_vt [bh][dh][s-pairs]. Runs after qkv.
// ---------------------------------------------------------------------------
__global__ void prep_vt_kernel()
{
    const int bh = blockIdx.y, s0 = blockIdx.x * 8;
    const int dh = threadIdx.x & 63, sp = threadIdx.x >> 6;
    const int s = s0 + 2 * sp;
    const float* vb = g_v + ((size_t)bh * SS + s) * DH + dh;
    uint2* dst = (uint2*)&g_vt[bh][dh][0];
    dst[(s0 >> 1) + sp] = split2(vb[0], vb[DH]);
}

// ---------------------------------------------------------------------------
// QKV projections from pre-split X/W; writes q,k pre-split, v fp32.
// q pre-scaled by 0.125*log2(e) so score's softmax uses bare ex2.
// ---------------------------------------------------------------------------
__global__ __launch_bounds__(256, 2) void qkv_proj_kernel(
    const float* __restrict__ bq, const float* __restrict__ bk,
    const float* __restrict__ bv)
{
    extern __shared__ char dynraw[];
    GemmSmem& sm = *reinterpret_cast<GemmSmem*>(dynraw);
    const int z = blockIdx.z;
    const float* bias = (z == 0) ? bq : (z == 1) ? bk : bv;
    const float scale = (z == 0) ? 0.125f * 1.4426950408889634f : 1.0f;

    const int rowBase = blockIdx.y * 128, colBase = blockIdx.x * 128;
    float acc[2][8][4] = {};
    gemm_sp_core(&g_spX[z][rowBase][0], DD / 4, &g_spW[z][colBase][0], DD / 4,
                 DD / 16, sm, acc);

    const int lane = threadIdx.x & 31, warp = threadIdx.x >> 5;
    const int tig = lane & 3, gid = lane >> 2;
    const int wr = (warp & 3) * 32, wc = (warp >> 2) * 64;
    #pragma unroll
    for (int mt = 0; mt < 2; mt++)
        #pragma unroll
        for (int nt = 0; nt < 8; nt++) {
            int col = colBase + wc + nt * 8 + 2 * tig;
            float2 bb = *(const float2*)&bias[col];
            int h = col >> 6, dh = col & 63;
            #pragma unroll
            for (int half = 0; half < 2; half++) {
                int row = rowBase + wr + mt * 16 + gid + 8 * half;
                int b = row >> 11, s = row & (SS - 1);
                float2 w;
                w.x = (acc[mt][nt][2 * half + 0] + bb.x) * scale;
                w.y = (acc[mt][nt][2 * half + 1] + bb.y) * scale;
                if (z < 2) {
                    uint2* dst = (uint2*)&g_qk[z][b * HH + h][s][0];
                    dst[dh >> 1] = split2(w.x, w.y);
                } else {
                    *(float2*)&g_v[(((size_t)(b * HH + h)) * SS + s) * DH + dh] = w;
                }
            }
        }
}

// ---------------------------------------------------------------------------
// Scores: P_unnorm = 2^(q@k^T) (q pre-scaled by 0.125*log2e) into attn buffer,
// partial row sums to g_psum. Epilogue staged through smem -> fully coalesced
// float4 row writes. Upper-triangle CTAs write the zero tail instead.
// ---------------------------------------------------------------------------
__global__ __launch_bounds__(256, 2) void score_kernel(float* __restrict__ scores)
{
    const int bh = blockIdx.z, rt = blockIdx.y, ct = blockIdx.x;
    float* outp = scores + (size_t)bh * SS * SS;

    if (ct > rt) {      // masked block: write exact zeros
        const int rowBase = rt * 128, colBase = ct * 128;
        const float4 z = make_float4(0.f, 0.f, 0.f, 0.f);
        #pragma unroll
        for (int i = 0; i < 8; i++) {
            int idx = threadIdx.x + i * 256;
            int r = idx >> 4, c4 = idx & 15;
            *(float4*)&outp[(size_t)(rowBase + r) * SS + colBase + c4 * 4] = z;
        }
        return;
    }

    extern __shared__ char dynraw[];
    GemmSmem& sm = *reinterpret_cast<GemmSmem*>(dynraw);
    __shared__ float rsum[2][128];

    const int rowBase = rt * 128, colBase = ct * 128;
    float acc[2][8][4] = {};
    gemm_sp_core(&g_qk[0][bh][rowBase][0], DH / 4, &g_qk[1][bh][colBase][0], DH / 4,
                 DH / 16, sm, acc);

    const int tid = threadIdx.x;
    const int lane = tid & 31, warp = tid >> 5;
    const int tig = lane & 3, gid = lane >> 2;
    const int wg = warp & 3, grp = warp >> 2, wc = grp * 64;
    const bool diag = (rt == ct);

    // staged epilogue: reuse GEMM smem (dead after mainloop) as float S[64][132]
    __syncthreads();
    float (*S)[132] = reinterpret_cast<float(*)[132]>(dynraw);

    float sums[2][2] = {};
    #pragma unroll
    for (int mt = 0; mt < 2; mt++) {
        #pragma unroll
        for (int nt = 0; nt < 8; nt++) {
            const int scol = wc + nt * 8 + 2 * tig;
            #pragma unroll
            for (int half = 0; half < 2; half++) {
                const int lr = wg * 16 + gid + 8 * half;        // 0..63
                const int rL = wg * 32 + mt * 16 + gid + 8 * half;
                float p0 = (!diag || scol     <= rL) ? ex2f(acc[mt][nt][2*half+0]) : 0.f;
                float p1 = (!diag || scol + 1 <= rL) ? ex2f(acc[mt][nt][2*half+1]) : 0.f;
                sums[mt][half] += p0 + p1;
                S[lr][scol]     = p0;
                S[lr][scol + 1] = p1;
            }
        }
        __syncthreads();
        #pragma unroll
        for (int it = 0; it < 8; it++) {
            int idx = it * 256 + tid;
            int lr = idx >> 5, c4 = (idx & 31) << 2;
            int grow = (lr >> 4) * 32 + mt * 16 + (lr & 15);
            *(float4*)&outp[(size_t)(rowBase + grow) * SS + colBase + c4] =
                *(const float4*)&S[lr][c4];
        }
        __syncthreads();
    }

    #pragma unroll
    for (int o = 1; o <= 2; o <<= 1)
        #pragma unroll
        for (int mt = 0; mt < 2; mt++)
            #pragma unroll
            for (int half = 0; half < 2; half++)
                sums[mt][half] += __shfl_xor_sync(0xffffffffu, sums[mt][half], o);
    if (tig == 0)
        #pragma unroll
        for (int mt = 0; mt < 2; mt++)
            #pragma unroll
            for (int half = 0; half < 2; half++)
                rsum[grp][wg * 32 + mt * 16 + gid + 8 * half] = sums[mt][half];
    __syncthreads();
    if (tid < 128)
        g_psum[(((size_t)(bh * 16 + rt) * 128) + tid) * 16 + ct] =
            rsum[0][tid] + rsum[1][tid];
}

// ---------------------------------------------------------------------------
// Context: normalize P on the fly (writes normalized attn_prob back),
// O = P@V via pre-split V^T (cp.async). Output -> g_ctxsp (pre-split).
// ---------------------------------------------------------------------------
struct CtxSmem { uint2 Ps[2][128][12]; uint2 Vs[2][64][12]; float sinv[128]; };

__global__ __launch_bounds__(256, 2) void context_kernel(float* __restrict__ scores)
{
    __shared__ CtxSmem sm;

    const int bh = blockIdx.z;
    const int rb = (int)(gridDim.x - 1) - (int)blockIdx.x;   // heavy first
    const int rowBase = rb * 128;
    float* P = scores + (size_t)bh * SS * SS + (size_t)rowBase * SS;
    const uint4* Vt = &g_vt[bh][0][0];
    const int kTiles = (rb + 1) * 8;

    const int tid  = threadIdx.x;
    const int lane = tid & 31, warp = tid >> 5;
    const int tig  = lane & 3, gid = lane >> 2;
    const int fr0  = tid >> 2, fr1 = fr0 + 64;
    const int fc   = (tid & 3) << 2;
    const int fp   = (tid & 3) << 1;
    const int vr   = tid >> 2, vq = tid & 3;

    if (tid < 128) {
        const float* pp = &g_psum[(((size_t)(bh * 16 + rb) * 128) + tid) * 16];
        float l = 0.f;
        for (int c = 0; c <= rb; c++) l += pp[c];
        sm.sinv[tid] = 1.0f / l;
    }
    __syncthreads();
    const float iv0 = sm.sinv[fr0], iv1 = sm.sinv[fr1];

    float4 va0, va1;
    auto prefA = [&](int kt) {
        const float* P2 = P + kt * 16;
        va0 = *(const float4*)(P2 + (size_t)fr0 * SS + fc);
        va1 = *(const float4*)(P2 + (size_t)fr1 * SS + fc);
    };
    auto issueB = [&](int s, int kt) {
        cp16(&sm.Vs[s][vr][vq * 2], Vt + (size_t)vr * (SS / 4) + kt * 4 + vq);
        CP_COMMIT();
    };
    auto stashA = [&](int s, int ktI) {
        float4 p0, p1;
        p0.x = va0.x * iv0; p0.y = va0.y * iv0; p0.z = va0.z * iv0; p0.w = va0.w * iv0;
        p1.x = va1.x * iv1; p1.y = va1.y * iv1; p1.z = va1.z * iv1; p1.w = va1.w * iv1;
        *(float4*)(P + (size_t)fr0 * SS + ktI * 16 + fc) = p0;   // normalized attn_prob
        *(float4*)(P + (size_t)fr1 * SS + ktI * 16 + fc) = p1;
        sm.Ps[s][fr0][fp]     = split2(p0.x, p0.y);
        sm.Ps[s][fr0][fp + 1] = split2(p0.z, p0.w);
        sm.Ps[s][fr1][fp]     = split2(p1.x, p1.y);
        sm.Ps[s][fr1][fp + 1] = split2(p1.z, p1.w);
    };

    float oacc[8][4] = {};
    prefA(0); issueB(0, 0); stashA(0, 0);
    CP_WAIT0();
    __syncthreads();

    for (int kt = 0; kt < kTiles; kt++) {
        const int s = kt & 1;
        const bool more = (kt + 1 < kTiles);
        if (more) { prefA(kt + 1); issueB(s ^ 1, kt + 1); }
        uint2 qa[4];
        const int rA = warp * 16 + gid;
        qa[0] = sm.Ps[s][rA][tig];
        qa[1] = sm.Ps[s][rA + 8][tig];
        qa[2] = sm.Ps[s][rA][tig + 4];
        qa[3] = sm.Ps[s][rA + 8][tig + 4];
        #pragma unroll
        for (int nt = 0; nt < 8; nt++) {
            const int cB = nt * 8 + gid;
            uint2 qb0 = sm.Vs[s][cB][tig];
            uint2 qb1 = sm.Vs[s][cB][tig + 4];
            mma3_bf(oacc[nt], qa, qb0, qb1);
        }
        if (more) stashA(s ^ 1, kt + 1);
        CP_WAIT0();
        __syncthreads();
    }

    const int b = bh >> 4, h = bh & 15;
    #pragma unroll
    for (int nt = 0; nt < 8; nt++) {
        int col = nt * 8 + 2 * tig;
        #pragma unroll
        for (int half = 0; half < 2; half++) {
            int s = rowBase + warp * 16 + gid + 8 * half;
            float2 w;
            w.x = oacc[nt][2 * half + 0];
            w.y = oacc[nt][2 * half + 1];
            uint2* dst = (uint2*)&g_ctxsp[b * SS + s][0];
            dst[(h * DH + col) >> 1] = split2(w.x, w.y);
        }
    }
}

// ---------------------------------------------------------------------------
// Output projection from pre-split ctx and Wo.
// ---------------------------------------------------------------------------
__global__ __launch_bounds__(256, 2) void outproj_kernel(
    const float* __restrict__ bo, float* __restrict__ out)
{
    extern __shared__ char dynraw[];
    GemmSmem& sm = *reinterpret_cast<GemmSmem*>(dynraw);
    const int rowBase = blockIdx.y * 128, colBase = blockIdx.x * 128;
    float acc[2][8][4] = {};
    gemm_sp_core(&g_ctxsp[rowBase][0], DD / 4, &g_spW[3][colBase][0], DD / 4,
                 DD / 16, sm, acc);

    const int lane = threadIdx.x & 31, warp = threadIdx.x >> 5;
    const int tig = lane & 3, gid = lane >> 2;
    const int wr = (warp & 3) * 32, wc = (warp >> 2) * 64;
    #pragma unroll
    for (int mt = 0; mt < 2; mt++)
        #pragma unroll
        for (int nt = 0; nt < 8; nt++) {
            int col = colBase + wc + nt * 8 + 2 * tig;
            float2 bb = *(const float2*)&bo[col];
            #pragma unroll
            for (int half = 0; half < 2; half++) {
                int row = rowBase + wr + mt * 16 + gid + 8 * half;
                float2 w;
                w.x = acc[mt][nt][2 * half + 0] + bb.x;
                w.y = acc[mt][nt][2 * half + 1] + bb.y;
                *(float2*)&out[(size_t)row * DD + col] = w;
            }
        }
}

// ---------------------------------------------------------------------------
extern "C" void kernel_launch(void* const* d_in, const int* in_sizes, int n_in,
                              void* d_out, int out_size)
{
    const float* Q  = (const float*)d_in[0];
    const float* K  = (const float*)d_in[1];
    const float* V  = (const float*)d_in[2];
    // d_in[3] = attn_mask: causal triu(k=1); applied analytically, not read.
    const float* Wq = (const float*)d_in[4];
    const float* bq = (const float*)d_in[5];
    const float* Wk = (const float*)d_in[6];
    const float* bk = (const float*)d_in[7];
    const float* Wv = (const float*)d_in[8];
    const float* bv = (const float*)d_in[9];
    const float* Wo = (const float*)d_in[10];
    const float* bo = (const float*)d_in[11];

    float* out  = (float*)d_out;                       // [B,S,D]
    float* attn = out + (size_t)BB * SS * DD;          // [B,H,S,S]

    const int GSM = (int)sizeof(GemmSmem);             // 48KB
    cudaFuncSetAttribute(qkv_proj_kernel, cudaFuncAttributeMaxDynamicSharedMemorySize, GSM);
    cudaFuncSetAttribute(score_kernel,    cudaFuncAttributeMaxDynamicSharedMemorySize, GSM);
    cudaFuncSetAttribute(outproj_kernel,  cudaFuncAttributeMaxDynamicSharedMemorySize, GSM);

    split_mats_kernel<<<dim3(BB*SS, 7), 256>>>(Q, K, V, Wq, Wk, Wv, Wo);
    qkv_proj_kernel <<<dim3(DD/128, (BB*SS)/128, 3), 256, GSM>>>(bq, bk, bv);
    prep_vt_kernel  <<<dim3(SS/8, BB*HH), 256>>>();
    score_kernel    <<<dim3(SS/128, SS/128, BB*HH), 256, GSM>>>(attn);
    context_kernel  <<<dim3(SS/128, 1, BB*HH), 256>>>(attn);
    outproj_kernel  <<<dim3(DD/128, (BB*SS)/128), 256, GSM>>>(bo, out);
}